// round 3
// baseline (speedup 1.0000x reference)
#include <cuda_runtime.h>
#include <math.h>

#define NR   512
#define NO   64
#define NT   20
#define NS   300
#define NBUF 400
#define WIN  48
#define NCTA 32
#define TPB  512
#define NTH  (NCTA*TPB)
#define KPT  16
#define DT_F 0.0001f
#define UUB  500.0f

__device__ float g_wl[NR*NR];
__device__ float g_rsum[NR];
__device__ float g_rssq[NR];
__device__ float g_dgd[NR];
__device__ float g_invnorm;
__device__ float g_pkw[KPT*NTH];
__device__ int   g_pko[KPT*NTH];
__device__ float g_lmt[NO*NR];
__device__ float g_Mbuf[2][NR];
__device__ float g_EI[NR];
__device__ int   g_cnt[2][NCTA][8];   // 32B-padded per-CTA step counters

__device__ __forceinline__ int ld_acquire_gpu(const int* p) {
    int v;
    asm volatile("ld.global.acquire.gpu.b32 %0, [%1];" : "=r"(v) : "l"(p) : "memory");
    return v;
}
__device__ __forceinline__ void red_release_gpu(int* p, int v) {
    asm volatile("red.release.gpu.global.add.s32 [%0], %1;" :: "l"(p), "r"(v) : "memory");
}

// ---------------- P1: w_l rows + per-row sum / sumsq ----------------
__global__ void k_p1(const float* __restrict__ wbb, const float* __restrict__ sc)
{
    int i = blockIdx.x;
    int t = threadIdx.x;
    float a = expf(wbb[i*NR + t]) * sc[i*NR + t];
    float b = expf(wbb[t*NR + i]) * sc[t*NR + i];
    float wl = log1pf(0.5f * (a + b));
    g_wl[i*NR + t] = wl;

    float s1 = wl, s2 = wl * wl;
    #pragma unroll
    for (int off = 16; off; off >>= 1) {
        s1 += __shfl_down_sync(0xffffffffu, s1, off);
        s2 += __shfl_down_sync(0xffffffffu, s2, off);
    }
    __shared__ float sA[16], sB[16];
    int w = t >> 5, l = t & 31;
    if (l == 0) { sA[w] = s1; sB[w] = s2; }
    __syncthreads();
    if (w == 0) {
        float r1 = (l < 16) ? sA[l] : 0.f;
        float r2 = (l < 16) ? sB[l] : 0.f;
        #pragma unroll
        for (int off = 8; off; off >>= 1) {
            r1 += __shfl_down_sync(0xffffffffu, r1, off);
            r2 += __shfl_down_sync(0xffffffffu, r2, off);
        }
        if (l == 0) { g_rsum[i] = r1; g_rssq[i] = r2; }
    }
}

// ---------------- P2: norm, dg diagonal, counter reset ----------------
__global__ void k_p2()
{
    int t = threadIdx.x;
    ((int*)&g_cnt[0][0][0])[t] = 0;   // 2*32*8 = 512 ints, one per thread

    float s2 = g_rssq[t];
    #pragma unroll
    for (int off = 16; off; off >>= 1) s2 += __shfl_down_sync(0xffffffffu, s2, off);
    __shared__ float sB[16];
    __shared__ float s_inv;
    int w = t >> 5, l = t & 31;
    if (l == 0) sB[w] = s2;
    __syncthreads();
    if (w == 0) {
        float r2 = (l < 16) ? sB[l] : 0.f;
        #pragma unroll
        for (int off = 8; off; off >>= 1) r2 += __shfl_down_sync(0xffffffffu, r2, off);
        if (l == 0) {
            float inv = 1.0f / sqrtf(r2);
            s_inv = inv;
            g_invnorm = inv;
        }
    }
    __syncthreads();
    g_dgd[t] = -s_inv * g_rsum[t];
}

// ---------------- P3: pack per-thread (weight, smem byte offset) ----------------
__global__ void k_p3(const float* __restrict__ dist, const float* __restrict__ theta)
{
    int id = blockIdx.x * TPB + threadIdx.x;
    int k   = id >> 14;
    int gt  = id & 16383;
    int c   = gt >> 9;
    int rem = gt & 511;
    int w2  = rem >> 5;
    int l   = rem & 31;
    int i   = c * 16 + w2;
    int j   = l + (k << 5);

    g_pkw[k*NTH + gt] = g_wl[i*NR + j] * g_invnorm;

    float denom = 1.5f + fmaxf(theta[16], 0.0f);
    float q = dist[j*NR + i] / denom;
    int d = (int)q;
    if (d < 0) d = 0;
    if (d > NBUF - 1) d = NBUF - 1;
    if (d > WIN - 1)  d = WIN - 1;
    g_pko[k*NTH + gt] = ((WIN - d) * NR + j) * 4;
}

// ---------------- P4: lm_t ----------------
__global__ void k_p4(const float* __restrict__ lm)
{
    int t = threadIdx.x;
    __shared__ float srs[NO];
    if (t < NO) {
        float s = 0.f;
        for (int i = 0; i < NR; i++) s += fabsf(lm[t*NR + i]);
        srs[t] = s;
    }
    __syncthreads();
    float cm = 0.f;
    for (int o = 0; o < NO; o++) cm += lm[o*NR + t] / srs[o];
    cm *= (1.0f / (float)NO);
    for (int o = 0; o < NO; o++) g_lmt[o*NR + t] = lm[o*NR + t] / srs[o] - cm;
}

// ---------------- main persistent kernel ----------------
__global__ void __launch_bounds__(TPB, 1)
jr_main(const float* __restrict__ theta,
        const float* __restrict__ hx,
        const float* __restrict__ hE0,
        const float* __restrict__ ext,
        const float* __restrict__ noise,
        float* __restrict__ out)
{
    extern __shared__ float sm[];
    float* hist = sm;                    // [2*WIN][NR]

    const int tid = threadIdx.x;
    const int c   = blockIdx.x;
    const int w   = tid >> 5;
    const int l   = tid & 31;
    const int gt  = c * TPB + tid;

    float wk[KPT]; int ok[KPT];
    #pragma unroll
    for (int k = 0; k < KPT; k++) {
        wk[k] = g_pkw[k*NTH + gt];
        ok[k] = g_pko[k*NTH + gt];
    }

    for (int idx = tid; idx < WIN*NR; idx += TPB) {
        int q = idx >> 9;
        int j = idx & 511;
        int cc = (WIN - q) % WIN;
        float v = hE0[j*NBUF + cc];
        hist[q*NR + j]       = v;
        hist[(q+WIN)*NR + j] = v;
    }

    // scalars (uniform, all threads)
    const float A_ = theta[0],  a_ = theta[1],  B_ = theta[2],  b_ = theta[3];
    const float gg = 0.01f + fmaxf(theta[4], 0.f);
    const float gf = 0.01f + fmaxf(theta[5], 0.f);
    const float gb = 0.01f + fmaxf(theta[6], 0.f);
    const float c1 = theta[7],  c2 = theta[8],  c3 = theta[9],  c4 = theta[10];
    const float rstd  = fmaxf(theta[11], 0.f);
    const float ncoef = 150.f + rstd;
    const float vmax = theta[12], v0 = theta[13], r_ = theta[14], y0_ = theta[15];
    const float ku   = (0.5f + fmaxf(theta[17], 0.f)) * theta[18];
    const float cy0  = theta[19];

    // warp w's lane 0 owns region i_reg
    const int i_reg = c*16 + w;
    float M=0,E=0,I=0,Mv=0,Ev=0,Iv=0,dgd_i=0;
    if (l == 0) {
        M  = hx[i_reg*6 + 0]; E  = hx[i_reg*6 + 1]; I  = hx[i_reg*6 + 2];
        Mv = hx[i_reg*6 + 3]; Ev = hx[i_reg*6 + 4]; Iv = hx[i_reg*6 + 5];
        dgd_i = g_dgd[i_reg];
    }
    __syncthreads();

    // software-pipelined inputs for step (wnd=0, s=0)
    float u_=0, n0=0, n1=0, n2=0;
    if (l == 0) {
        n0 = __ldg(noise + i_reg);
        n1 = __ldg(noise + NR + i_reg);
        n2 = __ldg(noise + 2*NR + i_reg);
        u_ = __ldg(ext + i_reg*(NS*NT));
    }

    int n = 1;          // global step (1..6000)
    int qq = 1;         // n % WIN
    int pbase = 0;      // history base row * NR for current step's gather

    for (int wnd = 0; wnd < NT; ++wnd) {
        for (int s = 0; s < NS; ++s) {
            const int par = n & 1;

            // lane 0: transcendental precompute from OLD state (overlaps gather)
            float rMb=0, rEb=0, rIb=0, EmI=0, Mn=0, En=0, In=0;
            if (l == 0) {
                EmI = E - I;
                float S0 = vmax / (1.f + expf(r_ * (v0 - EmI)));
                float S1 = vmax / (1.f + expf(r_ * (v0 - c1*M)));
                float S2 = vmax / (1.f + expf(r_ * (v0 - c3*M)));
                rMb = ku*u_ + rstd*n0 + S0;
                rEb = ncoef*n1 + c2*S1;
                rIb = ncoef*n2 + c4*S2;
                Mn = M + DT_F*Mv;
                En = E + DT_F*Ev;
                In = I + DT_F*Iv;
            }

            // lane 0: issue next step's input loads (hidden under gather+poll)
            {
                int sn = s + 1, wn = wnd;
                if (sn == NS) { sn = 0; wn = wnd + 1; if (wn == NT) { wn = NT-1; sn = NS-1; } }
                if (l == 0) {
                    const float* nb = noise + (size_t)(wn*NS + sn) * 3 * NR + i_reg;
                    n0 = __ldg(nb); n1 = __ldg(nb + NR); n2 = __ldg(nb + 2*NR);
                    u_ = __ldg(ext + i_reg*(NS*NT) + sn*NT + wn);
                }
            }

            // ---- delayed coupling gather (bank-conflict-free LDS) ----
            const char* hrow = (const char*)(hist + pbase);
            float acc0 = 0.f, acc1 = 0.f;
            #pragma unroll
            for (int k = 0; k < KPT; k += 2) {
                acc0 = fmaf(wk[k],   *(const float*)(hrow + ok[k]),   acc0);
                acc1 = fmaf(wk[k+1], *(const float*)(hrow + ok[k+1]), acc1);
            }
            float acc = acc0 + acc1;
            #pragma unroll
            for (int off = 16; off; off >>= 1)
                acc += __shfl_down_sync(0xffffffffu, acc, off);

            // ---- lane 0: finish update, publish M, arrive ----
            if (l == 0) {
                float LEd  = acc;
                float lmt_ = LEd + dgd_i * M;      // old M
                float let_ = LEd + dgd_i * EmI;    // old E-I
                float rM = rMb + gg*lmt_;
                float rE = rEb + gf*let_;
                float rI = rIb - gb*let_;
                float uM = UUB * tanhf(rM * (1.f/UUB));
                float uE = UUB * tanhf(rE * (1.f/UUB));
                float uI = UUB * tanhf(rI * (1.f/UUB));
                float Mvn = Mv + DT_F*(A_*a_*uM - 2.f*a_*Mv - a_*a_*M);
                float Evn = Ev + DT_F*(A_*a_*uE - 2.f*a_*Ev - a_*a_*E);
                float Ivn = Iv + DT_F*(B_*b_*uI - 2.f*b_*Iv - b_*b_*I);
                M = Mn; E = En; I = In; Mv = Mvn; Ev = Evn; Iv = Ivn;
                __stcg(&g_Mbuf[par][i_reg], M);
                if (s == NS-1) __stcg(&g_EI[i_reg], E - I);
                red_release_gpu(&g_cnt[par][c][0], 1);   // release-arrive for this region
            }

            // ---- decentralized wait + distributed ingest ----
            const int target = 16 * ((n + par) >> 1);   // uses of this parity so far
            if (l == 0)  { while (ld_acquire_gpu(&g_cnt[par][w][0])      < target) { } }
            if (l == 16) { while (ld_acquire_gpu(&g_cnt[par][w + 16][0]) < target) { } }
            __syncwarp();
            {
                int src = (l < 16) ? w : (w + 16);
                int j = src*16 + (l & 15);
                float v = __ldcg(&g_Mbuf[par][j]);
                hist[qq*NR + j]       = v;
                hist[(qq+WIN)*NR + j] = v;
            }

            // ---- EEG at window end (warps 8/9 -> channels 2c, 2c+1) ----
            if (s == NS-1 && (w == 8 || w == 9)) {
                // need ALL CTAs' g_EI: each lane polls one CTA's counter
                while (ld_acquire_gpu(&g_cnt[par][l][0]) < target) { }
                __syncwarp();
                int o = 2*c + (w - 8);
                float sacc = 0.f;
                #pragma unroll
                for (int m = 0; m < 16; m++) {
                    int i2 = l + 32*m;
                    sacc = fmaf(__ldg(&g_lmt[o*NR + i2]), __ldcg(&g_EI[i2]), sacc);
                }
                #pragma unroll
                for (int off = 16; off; off >>= 1)
                    sacc += __shfl_down_sync(0xffffffffu, sacc, off);
                if (l == 0) out[o*NT + wnd] = cy0 * sacc - y0_;
            }

            __syncthreads();            // hist ingest visible to all warps
            pbase = qq * NR;
            qq++; if (qq == WIN) qq = 0;
            n++;
        }
    }
}

extern "C" void kernel_launch(void* const* d_in, const int* in_sizes, int n_in,
                              void* d_out, int out_size)
{
    const float* theta = (const float*)d_in[0];
    const float* lm    = (const float*)d_in[1];
    const float* wbb   = (const float*)d_in[2];
    const float* sc    = (const float*)d_in[3];
    const float* dist  = (const float*)d_in[4];
    const float* hx    = (const float*)d_in[5];
    const float* hE0   = (const float*)d_in[6];
    const float* ext   = (const float*)d_in[7];
    const float* noise = (const float*)d_in[8];
    float* out = (float*)d_out;

    (void)in_sizes; (void)n_in; (void)out_size;

    const size_t SMEM = (size_t)(2*WIN*NR + 32) * sizeof(float);
    cudaFuncSetAttribute(jr_main, cudaFuncAttributeMaxDynamicSharedMemorySize, (int)SMEM);

    k_p1<<<NR, TPB>>>(wbb, sc);
    k_p2<<<1, TPB>>>();
    k_p3<<<(KPT*NTH)/TPB, TPB>>>(dist, theta);
    k_p4<<<1, TPB>>>(lm);
    jr_main<<<NCTA, TPB, SMEM>>>(theta, hx, hE0, ext, noise, out);
}

// round 5
// speedup vs baseline: 1.2783x; 1.2783x over previous
#include <cuda_runtime.h>
#include <stdint.h>
#include <math.h>

#define NR   512
#define NO   64
#define NT   20
#define NS   300
#define NBUF 400
#define WIN  48
#define DT_F 0.0001f
#define UUB  500.0f

// fallback (R2) geometry
#define NCTA  32
#define TPB   512
#define NTH   (NCTA*TPB)
#define KPT   16
// cluster geometry
#define NCTA2 16
#define NTH2  (NCTA2*TPB)   // 8192
#define KPT2  32

__device__ float g_wl[NR*NR];
__device__ float g_rsum[NR];
__device__ float g_rssq[NR];
__device__ float g_dgd[NR];
__device__ float g_invnorm;
__device__ float g_pkw[KPT*NTH];   // 262144 entries, shared by both mappings
__device__ int   g_pko[KPT*NTH];
__device__ float g_lmt[NO*NR];
__device__ float g_Mbuf[2][NR];
__device__ float g_EI[NR];
__device__ int   g_count;

__device__ __forceinline__ int ld_acquire_gpu(const int* p) {
    int v;
    asm volatile("ld.global.acquire.gpu.b32 %0, [%1];" : "=r"(v) : "l"(p) : "memory");
    return v;
}
__device__ __forceinline__ void red_release_gpu(int* p, int v) {
    asm volatile("red.release.gpu.global.add.s32 [%0], %1;" :: "l"(p), "r"(v) : "memory");
}
__device__ __forceinline__ uint32_t smem_u32(const void* p) {
    uint32_t a;
    asm("{ .reg .u64 t; cvta.to.shared.u64 t, %1; cvt.u32.u64 %0, t; }" : "=r"(a) : "l"(p));
    return a;
}
__device__ __forceinline__ uint32_t mapa_u32(uint32_t laddr, uint32_t rank) {
    uint32_t r;
    asm("mapa.shared::cluster.u32 %0, %1, %2;" : "=r"(r) : "r"(laddr), "r"(rank));
    return r;
}
__device__ __forceinline__ void stc_f32(uint32_t raddr, float v) {
    asm volatile("st.shared::cluster.f32 [%0], %1;" :: "r"(raddr), "f"(v) : "memory");
}
#define CLUSTER_ARRIVE() asm volatile("barrier.cluster.arrive.aligned;" ::: "memory")
#define CLUSTER_WAIT()   asm volatile("barrier.cluster.wait.aligned;"   ::: "memory")

// ---------------- P1: w_l rows + per-row sum / sumsq ----------------
__global__ void k_p1(const float* __restrict__ wbb, const float* __restrict__ sc)
{
    int i = blockIdx.x;
    int t = threadIdx.x;
    float a = expf(wbb[i*NR + t]) * sc[i*NR + t];
    float b = expf(wbb[t*NR + i]) * sc[t*NR + i];
    float wl = log1pf(0.5f * (a + b));
    g_wl[i*NR + t] = wl;

    float s1 = wl, s2 = wl * wl;
    #pragma unroll
    for (int off = 16; off; off >>= 1) {
        s1 += __shfl_down_sync(0xffffffffu, s1, off);
        s2 += __shfl_down_sync(0xffffffffu, s2, off);
    }
    __shared__ float sA[16], sB[16];
    int w = t >> 5, l = t & 31;
    if (l == 0) { sA[w] = s1; sB[w] = s2; }
    __syncthreads();
    if (w == 0) {
        float r1 = (l < 16) ? sA[l] : 0.f;
        float r2 = (l < 16) ? sB[l] : 0.f;
        #pragma unroll
        for (int off = 8; off; off >>= 1) {
            r1 += __shfl_down_sync(0xffffffffu, r1, off);
            r2 += __shfl_down_sync(0xffffffffu, r2, off);
        }
        if (l == 0) { g_rsum[i] = r1; g_rssq[i] = r2; }
    }
}

// ---------------- P2: norm, dg diagonal, counter reset ----------------
__global__ void k_p2()
{
    int t = threadIdx.x;
    float s2 = g_rssq[t];
    #pragma unroll
    for (int off = 16; off; off >>= 1) s2 += __shfl_down_sync(0xffffffffu, s2, off);
    __shared__ float sB[16];
    __shared__ float s_inv;
    int w = t >> 5, l = t & 31;
    if (l == 0) sB[w] = s2;
    __syncthreads();
    if (w == 0) {
        float r2 = (l < 16) ? sB[l] : 0.f;
        #pragma unroll
        for (int off = 8; off; off >>= 1) r2 += __shfl_down_sync(0xffffffffu, r2, off);
        if (l == 0) {
            float inv = 1.0f / sqrtf(r2);
            s_inv = inv;
            g_invnorm = inv;
            g_count = 0;
        }
    }
    __syncthreads();
    g_dgd[t] = -s_inv * g_rsum[t];
}

// ---------------- P3a: packing for fallback (32 CTA) kernel ----------------
__global__ void k_p3a(const float* __restrict__ dist, const float* __restrict__ theta)
{
    int id = blockIdx.x * TPB + threadIdx.x;
    int k   = id >> 14;
    int gt  = id & 16383;
    int c   = gt >> 9;
    int rem = gt & 511;
    int w2  = rem >> 5;
    int l   = rem & 31;
    int i   = c * 16 + w2;
    int j   = l + (k << 5);

    g_pkw[k*NTH + gt] = g_wl[i*NR + j] * g_invnorm;

    float denom = 1.5f + fmaxf(theta[16], 0.0f);
    int d = (int)(dist[j*NR + i] / denom);
    if (d < 0) d = 0;
    if (d > WIN - 1) d = WIN - 1;
    g_pko[k*NTH + gt] = ((WIN - d) * NR + j) * 4;
}

// ---------------- P3b: packing for cluster (16 CTA) kernel ----------------
// lanes 0-15:  region i = c*32+2w,   j = l + 16k
// lanes 16-31: region i = c*32+2w+1, j = (l-16) + 16*((k+1)&31)  (bank stagger)
__global__ void k_p3b(const float* __restrict__ dist, const float* __restrict__ theta)
{
    int id = blockIdx.x * TPB + threadIdx.x;   // 0 .. KPT2*NTH2-1
    int k   = id >> 13;            // 0..31
    int gt  = id & 8191;
    int c   = gt >> 9;
    int rem = gt & 511;
    int w2  = rem >> 5;
    int l   = rem & 31;
    int i, j;
    if (l < 16) { i = c*32 + 2*w2;     j = l + 16*k; }
    else        { i = c*32 + 2*w2 + 1; j = (l - 16) + 16*((k + 1) & 31); }

    g_pkw[k*NTH2 + gt] = g_wl[i*NR + j] * g_invnorm;

    float denom = 1.5f + fmaxf(theta[16], 0.0f);
    int d = (int)(dist[j*NR + i] / denom);
    if (d < 0) d = 0;
    if (d > WIN - 1) d = WIN - 1;
    g_pko[k*NTH2 + gt] = ((WIN - d) * NR + j) * 4;
}

// ---------------- P4: lm_t ----------------
__global__ void k_p4(const float* __restrict__ lm)
{
    int t = threadIdx.x;
    __shared__ float srs[NO];
    if (t < NO) {
        float s = 0.f;
        for (int i = 0; i < NR; i++) s += fabsf(lm[t*NR + i]);
        srs[t] = s;
    }
    __syncthreads();
    float cm = 0.f;
    for (int o = 0; o < NO; o++) cm += lm[o*NR + t] / srs[o];
    cm *= (1.0f / (float)NO);
    for (int o = 0; o < NO; o++) g_lmt[o*NR + t] = lm[o*NR + t] / srs[o] - cm;
}

// =========================================================================
// CLUSTER kernel: 16 CTAs x 512 threads, one cluster, DSMEM broadcast
// =========================================================================
__global__ void __launch_bounds__(TPB, 1)
jr_cluster(const float* __restrict__ theta,
           const float* __restrict__ hx,
           const float* __restrict__ hE0,
           const float* __restrict__ ext,
           const float* __restrict__ noise,
           float* __restrict__ out)
{
    extern __shared__ float sm[];
    float* hist = sm;                    // [2*WIN][NR]
    float* sEI  = sm + 2*WIN*NR;         // [NR]

    const int tid = threadIdx.x;
    const int c   = blockIdx.x;          // == cluster rank (single cluster)
    const int w   = tid >> 5;
    const int l   = tid & 31;
    const int gt  = c * TPB + tid;

    float wk[KPT2]; int ok[KPT2];
    #pragma unroll
    for (int k = 0; k < KPT2; k++) {
        wk[k] = g_pkw[k*NTH2 + gt];
        ok[k] = g_pko[k*NTH2 + gt];
    }

    for (int idx = tid; idx < WIN*NR; idx += TPB) {
        int q = idx >> 9;
        int j = idx & 511;
        int cc = (WIN - q) % WIN;
        float v = hE0[j*NBUF + cc];
        hist[q*NR + j]       = v;
        hist[(q+WIN)*NR + j] = v;
    }

    const float A_ = theta[0],  a_ = theta[1],  B_ = theta[2],  b_ = theta[3];
    const float gg = 0.01f + fmaxf(theta[4], 0.f);
    const float gf = 0.01f + fmaxf(theta[5], 0.f);
    const float gb = 0.01f + fmaxf(theta[6], 0.f);
    const float c1 = theta[7],  c2 = theta[8],  c3 = theta[9],  c4 = theta[10];
    const float rstd  = fmaxf(theta[11], 0.f);
    const float ncoef = 150.f + rstd;
    const float vmax = theta[12], v0 = theta[13], r_ = theta[14], y0_ = theta[15];
    const float ku   = (0.5f + fmaxf(theta[17], 0.f)) * theta[18];
    const float cy0  = theta[19];

    // region ownership: warp w owns regions rA (lanes 0-15) and rA+1 (lanes 16-31)
    const int  rA    = c*32 + 2*w;
    const bool lead  = (l == 0) || (l == 16);
    const int  i_reg = rA + (l >= 16 ? 1 : 0);

    float M=0,E=0,I=0,Mv=0,Ev=0,Iv=0,dgd_i=0;
    if (lead) {
        M  = hx[i_reg*6 + 0]; E  = hx[i_reg*6 + 1]; I  = hx[i_reg*6 + 2];
        Mv = hx[i_reg*6 + 3]; Ev = hx[i_reg*6 + 4]; Iv = hx[i_reg*6 + 5];
        dgd_i = g_dgd[i_reg];
    }

    // DSMEM scatter targets: lane writes region rj to peer CTA (l & 15)
    const int      rj     = rA + (l >= 16 ? 1 : 0);
    const uint32_t sbase  = smem_u32(sm);
    const uint32_t rbase  = mapa_u32(sbase, (uint32_t)(l & 15));
    const uint32_t rj4    = (uint32_t)rj * 4u;
    const uint32_t eiOff  = (uint32_t)(2*WIN*NR) * 4u + rj4;

    __syncthreads();
    CLUSTER_ARRIVE();
    CLUSTER_WAIT();

    // pipelined inputs for step (0,0)
    float u_=0, n0=0, n1=0, n2=0;
    if (lead) {
        n0 = __ldg(noise + i_reg);
        n1 = __ldg(noise + NR + i_reg);
        n2 = __ldg(noise + 2*NR + i_reg);
        u_ = __ldg(ext + i_reg*(NS*NT));
    }

    int qq = 1;
    int pbase = 0;

    for (int wnd = 0; wnd < NT; ++wnd) {
        for (int s = 0; s < NS; ++s) {
            // lead lanes: transcendental precompute from OLD state
            float rMb=0, rEb=0, rIb=0, EmI=0, Mn=0, En=0, In=0;
            if (lead) {
                EmI = E - I;
                float S0 = vmax / (1.f + expf(r_ * (v0 - EmI)));
                float S1 = vmax / (1.f + expf(r_ * (v0 - c1*M)));
                float S2 = vmax / (1.f + expf(r_ * (v0 - c3*M)));
                rMb = ku*u_ + rstd*n0 + S0;
                rEb = ncoef*n1 + c2*S1;
                rIb = ncoef*n2 + c4*S2;
                Mn = M + DT_F*Mv;
                En = E + DT_F*Ev;
                In = I + DT_F*Iv;
            }
            // prefetch next step inputs
            {
                int sn = s + 1, wn = wnd;
                if (sn == NS) { sn = 0; wn = wnd + 1; if (wn == NT) { wn = NT-1; sn = NS-1; } }
                if (lead) {
                    const float* nb = noise + (size_t)(wn*NS + sn) * 3 * NR + i_reg;
                    n0 = __ldg(nb); n1 = __ldg(nb + NR); n2 = __ldg(nb + 2*NR);
                    u_ = __ldg(ext + i_reg*(NS*NT) + sn*NT + wn);
                }
            }

            // ---- gather: 32 terms/lane, conflict-free ----
            const char* hrow = (const char*)(hist + pbase);
            float acc0 = 0.f, acc1 = 0.f;
            #pragma unroll
            for (int k = 0; k < KPT2; k += 2) {
                acc0 = fmaf(wk[k],   *(const float*)(hrow + ok[k]),   acc0);
                acc1 = fmaf(wk[k+1], *(const float*)(hrow + ok[k+1]), acc1);
            }
            float acc = acc0 + acc1;
            // half-warp reduce (width 16): lanes 0 and 16 hold totals
            #pragma unroll
            for (int off = 8; off; off >>= 1)
                acc += __shfl_down_sync(0xffffffffu, acc, off, 16);

            // ---- lead lanes: finish update ----
            if (lead) {
                float LEd  = acc;
                float lmt_ = LEd + dgd_i * M;
                float let_ = LEd + dgd_i * EmI;
                float rM = rMb + gg*lmt_;
                float rE = rEb + gf*let_;
                float rI = rIb - gb*let_;
                float uM = UUB * tanhf(rM * (1.f/UUB));
                float uE = UUB * tanhf(rE * (1.f/UUB));
                float uI = UUB * tanhf(rI * (1.f/UUB));
                float Mvn = Mv + DT_F*(A_*a_*uM - 2.f*a_*Mv - a_*a_*M);
                float Evn = Ev + DT_F*(A_*a_*uE - 2.f*a_*Ev - a_*a_*E);
                float Ivn = Iv + DT_F*(B_*b_*uI - 2.f*b_*Iv - b_*b_*I);
                M = Mn; E = En; I = In; Mv = Mvn; Ev = Evn; Iv = Ivn;
            }

            // ---- DSMEM scatter of new M to all 16 CTAs (incl. self) ----
            float Mval = __shfl_sync(0xffffffffu, M, (l < 16) ? 0 : 16);
            uint32_t row0 = rbase + (uint32_t)(qq*NR)*4u + rj4;
            stc_f32(row0, Mval);
            stc_f32(row0 + (uint32_t)(WIN*NR)*4u, Mval);
            if (s == NS-1) {
                float EIval = __shfl_sync(0xffffffffu, E - I, (l < 16) ? 0 : 16);
                stc_f32(rbase + eiOff, EIval);
            }

            CLUSTER_ARRIVE();
            CLUSTER_WAIT();

            // ---- EEG at window end: warps 4..7 -> channels c*4 + (w-4) ----
            if (s == NS-1 && (w >= 4 && w < 8)) {
                int o = c*4 + (w - 4);
                float sacc = 0.f;
                #pragma unroll
                for (int m = 0; m < 16; m++) {
                    int i2 = l + 32*m;
                    sacc = fmaf(__ldg(&g_lmt[o*NR + i2]), sEI[i2], sacc);
                }
                #pragma unroll
                for (int off = 16; off; off >>= 1)
                    sacc += __shfl_down_sync(0xffffffffu, sacc, off);
                if (l == 0) out[o*NT + wnd] = cy0 * sacc - y0_;
            }

            pbase = qq * NR;
            qq++; if (qq == WIN) qq = 0;
        }
    }
}

// =========================================================================
// FALLBACK kernel: exact R2 design (32 CTAs, L2 counter sync) — known good
// =========================================================================
__global__ void __launch_bounds__(TPB, 1)
jr_main_fb(const float* __restrict__ theta,
           const float* __restrict__ hx,
           const float* __restrict__ hE0,
           const float* __restrict__ ext,
           const float* __restrict__ noise,
           float* __restrict__ out)
{
    extern __shared__ float sm[];
    float* hist  = sm;
    float* s_led = sm + 2*WIN*NR;

    const int tid = threadIdx.x;
    const int c   = blockIdx.x;
    const int w   = tid >> 5;
    const int l   = tid & 31;
    const int gt  = c * TPB + tid;

    float wk[KPT]; int ok[KPT];
    #pragma unroll
    for (int k = 0; k < KPT; k++) {
        wk[k] = g_pkw[k*NTH + gt];
        ok[k] = g_pko[k*NTH + gt];
    }

    for (int idx = tid; idx < WIN*NR; idx += TPB) {
        int q = idx >> 9;
        int j = idx & 511;
        int cc = (WIN - q) % WIN;
        float v = hE0[j*NBUF + cc];
        hist[q*NR + j]       = v;
        hist[(q+WIN)*NR + j] = v;
    }

    const float cy0 = theta[19];
    const float y0_ = theta[15];

    float M=0,E=0,I=0,Mv=0,Ev=0,Iv=0, dgd_i=0;
    float A_=0,a_=0,B_=0,b_=0,gg=0,gf=0,gb=0,c1=0,c2=0,c3=0,c4=0;
    float rstd=0,ncoef=0,vmax=0,v0=0,r_=0,ku=0;
    const int i_reg = c*16 + l;
    if (w == 0) {
        A_ = theta[0];  a_ = theta[1];  B_ = theta[2];  b_ = theta[3];
        gg = 0.01f + fmaxf(theta[4], 0.f);
        gf = 0.01f + fmaxf(theta[5], 0.f);
        gb = 0.01f + fmaxf(theta[6], 0.f);
        c1 = theta[7];  c2 = theta[8];  c3 = theta[9];  c4 = theta[10];
        rstd  = fmaxf(theta[11], 0.f);
        ncoef = 150.f + rstd;
        vmax = theta[12]; v0 = theta[13]; r_ = theta[14];
        ku   = (0.5f + fmaxf(theta[17], 0.f)) * theta[18];
        if (l < 16) {
            M  = hx[i_reg*6 + 0]; E  = hx[i_reg*6 + 1]; I  = hx[i_reg*6 + 2];
            Mv = hx[i_reg*6 + 3]; Ev = hx[i_reg*6 + 4]; Iv = hx[i_reg*6 + 5];
            dgd_i = g_dgd[i_reg];
        }
    }
    __syncthreads();

    int n = 1;
    int pbase = 0;

    for (int wnd = 0; wnd < NT; ++wnd) {
        for (int s = 0; s < NS; ++s) {
            float u_=0, n0=0, n1=0, n2=0;
            if (w == 0 && l < 16) {
                int t_lin = wnd*NS + s;
                const float* nb = noise + (size_t)t_lin * 3 * NR + i_reg;
                n0 = __ldg(nb); n1 = __ldg(nb + NR); n2 = __ldg(nb + 2*NR);
                u_ = __ldg(ext + i_reg*(NS*NT) + s*NT + wnd);
            }

            const char* hrow = (const char*)(hist + pbase);
            float acc0 = 0.f, acc1 = 0.f;
            #pragma unroll
            for (int k = 0; k < KPT; k += 2) {
                acc0 = fmaf(wk[k],   *(const float*)(hrow + ok[k]),   acc0);
                acc1 = fmaf(wk[k+1], *(const float*)(hrow + ok[k+1]), acc1);
            }
            float acc = acc0 + acc1;
            #pragma unroll
            for (int off = 16; off; off >>= 1)
                acc += __shfl_down_sync(0xffffffffu, acc, off);
            if (l == 0) s_led[w] = acc;
            __syncthreads();

            const int par = n & 1;

            if (w == 0) {
                if (l < 16) {
                    float LEd = s_led[l];
                    float EmI = E - I;
                    float S0 = vmax / (1.f + expf(r_ * (v0 - EmI)));
                    float S1 = vmax / (1.f + expf(r_ * (v0 - c1*M)));
                    float S2 = vmax / (1.f + expf(r_ * (v0 - c3*M)));
                    float lmt_ = LEd + dgd_i * M;
                    float let_ = LEd + dgd_i * EmI;
                    float rM = ku*u_ + rstd*n0 + gg*lmt_ + S0;
                    float rE = ncoef*n1 + gf*let_ + c2*S1;
                    float rI = ncoef*n2 - gb*let_ + c4*S2;
                    float Mn = M + DT_F*Mv;
                    float En = E + DT_F*Ev;
                    float In = I + DT_F*Iv;
                    float uM = UUB * tanhf(rM * (1.f/UUB));
                    float uE = UUB * tanhf(rE * (1.f/UUB));
                    float uI = UUB * tanhf(rI * (1.f/UUB));
                    float Mvn = Mv + DT_F*(A_*a_*uM - 2.f*a_*Mv - a_*a_*M);
                    float Evn = Ev + DT_F*(A_*a_*uE - 2.f*a_*Ev - a_*a_*E);
                    float Ivn = Iv + DT_F*(B_*b_*uI - 2.f*b_*Iv - b_*b_*I);
                    M = Mn; E = En; I = In; Mv = Mvn; Ev = Evn; Iv = Ivn;
                    __stcg(&g_Mbuf[par][i_reg], M);
                    if (s == NS-1) __stcg(&g_EI[i_reg], E - I);
                }
                __threadfence();
                if (l == 0) {
                    red_release_gpu(&g_count, 1);
                    const int target = NCTA * n;
                    while (ld_acquire_gpu(&g_count) < target) { }
                }
            }
            __syncthreads();

            {
                float v = __ldcg(&g_Mbuf[par][tid]);
                int q = n % WIN;
                hist[q*NR + tid]       = v;
                hist[(q+WIN)*NR + tid] = v;
            }

            if (s == NS-1 && (w == 8 || w == 9)) {
                int o = 2*c + (w - 8);
                float sacc = 0.f;
                #pragma unroll
                for (int m = 0; m < 16; m++) {
                    int i2 = l + 32*m;
                    sacc = fmaf(__ldg(&g_lmt[o*NR + i2]), __ldcg(&g_EI[i2]), sacc);
                }
                #pragma unroll
                for (int off = 16; off; off >>= 1)
                    sacc += __shfl_down_sync(0xffffffffu, sacc, off);
                if (l == 0) out[o*NT + wnd] = cy0 * sacc - y0_;
            }

            __syncthreads();
            pbase = (n % WIN) * NR;
            n++;
        }
    }
}

extern "C" void kernel_launch(void* const* d_in, const int* in_sizes, int n_in,
                              void* d_out, int out_size)
{
    const float* theta = (const float*)d_in[0];
    const float* lm    = (const float*)d_in[1];
    const float* wbb   = (const float*)d_in[2];
    const float* sc    = (const float*)d_in[3];
    const float* dist  = (const float*)d_in[4];
    const float* hx    = (const float*)d_in[5];
    const float* hE0   = (const float*)d_in[6];
    const float* ext   = (const float*)d_in[7];
    const float* noise = (const float*)d_in[8];
    float* out = (float*)d_out;

    (void)in_sizes; (void)n_in; (void)out_size;

    const size_t SMEM_FB = (size_t)(2*WIN*NR + 32) * sizeof(float);
    const size_t SMEM_CL = (size_t)(2*WIN*NR + NR) * sizeof(float);

    cudaFuncSetAttribute(jr_main_fb, cudaFuncAttributeMaxDynamicSharedMemorySize, (int)SMEM_FB);
    cudaError_t e1 = cudaFuncSetAttribute(jr_cluster, cudaFuncAttributeNonPortableClusterSizeAllowed, 1);
    cudaError_t e2 = cudaFuncSetAttribute(jr_cluster, cudaFuncAttributeMaxDynamicSharedMemorySize, (int)SMEM_CL);

    cudaLaunchConfig_t cfg = {};
    cfg.gridDim  = dim3(NCTA2, 1, 1);
    cfg.blockDim = dim3(TPB, 1, 1);
    cfg.dynamicSmemBytes = SMEM_CL;
    cfg.stream = 0;
    cudaLaunchAttribute at[1];
    at[0].id = cudaLaunchAttributeClusterDimension;
    at[0].val.clusterDim.x = NCTA2;
    at[0].val.clusterDim.y = 1;
    at[0].val.clusterDim.z = 1;
    cfg.attrs = at;
    cfg.numAttrs = 1;

    int ncl = 0;
    cudaError_t qe = cudaOccupancyMaxActiveClusters(&ncl, jr_cluster, &cfg);
    bool use_cluster = (e1 == cudaSuccess) && (e2 == cudaSuccess) &&
                       (qe == cudaSuccess) && (ncl >= 1);

    k_p1<<<NR, TPB>>>(wbb, sc);
    k_p2<<<1, TPB>>>();
    k_p4<<<1, TPB>>>(lm);

    if (use_cluster) {
        k_p3b<<<(KPT2*NTH2)/TPB, TPB>>>(dist, theta);
        cudaLaunchKernelEx(&cfg, jr_cluster, theta, hx, hE0, ext, noise, out);
    } else {
        k_p3a<<<(KPT*NTH)/TPB, TPB>>>(dist, theta);
        jr_main_fb<<<NCTA, TPB, SMEM_FB>>>(theta, hx, hE0, ext, noise, out);
    }
}